// round 15
// baseline (speedup 1.0000x reference)
#include <cuda_runtime.h>

// S=64, B=128, D=10000 fixed by the reference.
#define D_DIM   10000
#define D4      2500
#define NU      1250          // 32-byte units per row
#define NITER   39            // 39*32 = 1248 units; tail = 2 units (lane<2)
#define S_DIM   64
#define B_DIM   128
#define THREADS 512
#define NWARPS  16
#define SMEM_BYTES (2 * D_DIM * sizeof(float))   // 80000 B

#define L2E 1.4426950408889634f

__device__ float    g_partial[B_DIM];
__device__ unsigned g_ticket;      // zero-init; reset by last CTA each launch

__device__ __forceinline__ float ex2f(float x) {
    float r;
    asm("ex2.approx.ftz.f32 %0, %1;" : "=f"(r) : "f"(x));
    return r;
}

struct F8 { float4 a, b; };

// 256-bit streaming global load (sm_100a LDG.E.256)
__device__ __forceinline__ F8 ldg256cs(const void* p) {
    unsigned r0, r1, r2, r3, r4, r5, r6, r7;
    asm("ld.global.cs.v8.b32 {%0,%1,%2,%3,%4,%5,%6,%7}, [%8];"
        : "=r"(r0), "=r"(r1), "=r"(r2), "=r"(r3),
          "=r"(r4), "=r"(r5), "=r"(r6), "=r"(r7)
        : "l"(p));
    F8 v;
    v.a.x = __uint_as_float(r0); v.a.y = __uint_as_float(r1);
    v.a.z = __uint_as_float(r2); v.a.w = __uint_as_float(r3);
    v.b.x = __uint_as_float(r4); v.b.y = __uint_as_float(r5);
    v.b.z = __uint_as_float(r6); v.b.w = __uint_as_float(r7);
    return v;
}

// consume one quad (noise n, theta*log2e t, y yv) into one sample's accumulators
__device__ __forceinline__ void consume1(const float4& n, const float4& t,
                                         const float4& yv,
                                         float& sq, float& sq2, float& sqy)
{
    float qx = ex2f(fmaf(n.x, L2E, t.x));
    float qy = ex2f(fmaf(n.y, L2E, t.y));
    float qz = ex2f(fmaf(n.z, L2E, t.z));
    float qw = ex2f(fmaf(n.w, L2E, t.w));
    sq  += (qx + qy) + (qz + qw);
    sq2 = fmaf(qx, qx, sq2);   sq2 = fmaf(qy, qy, sq2);
    sq2 = fmaf(qz, qz, sq2);   sq2 = fmaf(qw, qw, sq2);
    sqy = fmaf(qx, yv.x, sqy); sqy = fmaf(qy, yv.y, sqy);
    sqy = fmaf(qz, yv.z, sqy); sqy = fmaf(qw, yv.w, sqy);
}

__global__ __launch_bounds__(THREADS, 1)   // 1 CTA/SM -> up to 128 regs/thread
void pl_fused(const float* __restrict__ theta,
              const float* __restrict__ y,
              const float* __restrict__ noise,
              float* __restrict__ out)
{
    extern __shared__ float sm[];          // [0,10000): theta_b*log2e  [10000,20000): y_b
    float* __restrict__ sth = sm;
    float* __restrict__ syy = sm + D_DIM;
    __shared__ float fin[NWARPS];
    __shared__ int   is_last;

    const int b    = blockIdx.x;
    const int tid  = threadIdx.x;
    const int lane = tid & 31;
    const int warp = tid >> 5;

    // ---- stage theta_b*log2e, y_b into shared; per-thread partial Sigma(y^2) ----
    float sy2p = 0.0f;
    {
        const float4* __restrict__ th4 = (const float4*)(theta + (size_t)b * D_DIM);
        const float4* __restrict__ yy4 = (const float4*)(y     + (size_t)b * D_DIM);
        float4* s_t = (float4*)sth;
        float4* s_y = (float4*)syy;
        for (int i = tid; i < D4; i += THREADS) {
            float4 t = __ldg(th4 + i);
            float4 v = __ldg(yy4 + i);
            sy2p = fmaf(v.x, v.x, sy2p);
            sy2p = fmaf(v.y, v.y, sy2p);
            sy2p = fmaf(v.z, v.z, sy2p);
            sy2p = fmaf(v.w, v.w, sy2p);
            t.x *= L2E; t.y *= L2E; t.z *= L2E; t.w *= L2E;
            s_t[i] = t;
            s_y[i] = v;
        }
    }
    __syncthreads();

    const float4* __restrict__ st4 = (const float4*)sth;
    const float4* __restrict__ sy4 = (const float4*)syy;

    // ---- single pass: warp owns samples 4*warp .. 4*warp+3 ----
    const size_t rowbytes = (size_t)B_DIM * D_DIM * sizeof(float); // sample stride
    const char* __restrict__ nz0 =
        (const char*)noise + ((size_t)(4 * warp) * B_DIM + b) * D_DIM * sizeof(float);
    const char* __restrict__ nz1 = nz0 + rowbytes;
    const char* __restrict__ nz2 = nz1 + rowbytes;
    const char* __restrict__ nz3 = nz2 + rowbytes;

    float q0 = 0.f, q0s = 0.f, q0y = 0.f;
    float q1 = 0.f, q1s = 0.f, q1y = 0.f;
    float q2 = 0.f, q2s = 0.f, q2y = 0.f;
    float q3 = 0.f, q3s = 0.f, q3y = 0.f;

    // depth-2 rotating pipeline per sample, 32-byte units (LDG.256)
    const size_t lb = (size_t)lane * 32;
    F8 P0[2], P1[2], P2[2], P3[2];
    #pragma unroll
    for (int k = 0; k < 2; k++) {
        const size_t off = (size_t)k * 1024 + lb;
        P0[k] = ldg256cs(nz0 + off);
        P1[k] = ldg256cs(nz1 + off);
        P2[k] = ldg256cs(nz2 + off);
        P3[k] = ldg256cs(nz3 + off);
    }

    // main: blocks 0..36 consume, reload block i+2 (last reload = block 38)
    #pragma unroll 2
    for (int i = 0; i <= 36; i++) {
        const int u  = i * 32 + lane;        // 32B-unit index
        const int k  = i & 1;
        const int f  = 2 * u;                // float4 index
        float4 t0 = st4[f],     y0 = sy4[f];
        float4 t1 = st4[f + 1], y1 = sy4[f + 1];
        consume1(P0[k].a, t0, y0, q0, q0s, q0y);
        consume1(P0[k].b, t1, y1, q0, q0s, q0y);
        consume1(P1[k].a, t0, y0, q1, q1s, q1y);
        consume1(P1[k].b, t1, y1, q1, q1s, q1y);
        consume1(P2[k].a, t0, y0, q2, q2s, q2y);
        consume1(P2[k].b, t1, y1, q2, q2s, q2y);
        consume1(P3[k].a, t0, y0, q3, q3s, q3y);
        consume1(P3[k].b, t1, y1, q3, q3s, q3y);
        const size_t off = (size_t)(u + 64) * 32;   // block i+2
        P0[k] = ldg256cs(nz0 + off);
        P1[k] = ldg256cs(nz1 + off);
        P2[k] = ldg256cs(nz2 + off);
        P3[k] = ldg256cs(nz3 + off);
    }

    // tail loads (lane<2): units 1248,1249 -> issued before epilogue consume
    F8 t0f, t1f, t2f, t3f;
    if (lane < 2) {
        const size_t off = (size_t)(1248 + lane) * 32;
        t0f = ldg256cs(nz0 + off);
        t1f = ldg256cs(nz1 + off);
        t2f = ldg256cs(nz2 + off);
        t3f = ldg256cs(nz3 + off);
    }

    // epilogue: blocks 37 (P[1]) and 38 (P[0]), no reloads
    #pragma unroll
    for (int i = 37; i <= 38; i++) {
        const int u = i * 32 + lane;
        const int k = i & 1;
        const int f = 2 * u;
        float4 t0 = st4[f],     y0 = sy4[f];
        float4 t1 = st4[f + 1], y1 = sy4[f + 1];
        consume1(P0[k].a, t0, y0, q0, q0s, q0y);
        consume1(P0[k].b, t1, y1, q0, q0s, q0y);
        consume1(P1[k].a, t0, y0, q1, q1s, q1y);
        consume1(P1[k].b, t1, y1, q1, q1s, q1y);
        consume1(P2[k].a, t0, y0, q2, q2s, q2y);
        consume1(P2[k].b, t1, y1, q2, q2s, q2y);
        consume1(P3[k].a, t0, y0, q3, q3s, q3y);
        consume1(P3[k].b, t1, y1, q3, q3s, q3y);
    }
    // tail units 1248..1249 (float4 idx 2496..2499)
    if (lane < 2) {
        const int f = 2 * (1248 + lane);
        float4 t0 = st4[f],     y0 = sy4[f];
        float4 t1 = st4[f + 1], y1 = sy4[f + 1];
        consume1(t0f.a, t0, y0, q0, q0s, q0y);
        consume1(t0f.b, t1, y1, q0, q0s, q0y);
        consume1(t1f.a, t0, y0, q1, q1s, q1y);
        consume1(t1f.b, t1, y1, q1, q1s, q1y);
        consume1(t2f.a, t0, y0, q2, q2s, q2y);
        consume1(t2f.b, t1, y1, q2, q2s, q2y);
        consume1(t3f.a, t0, y0, q3, q3s, q3y);
        consume1(t3f.b, t1, y1, q3, q3s, q3y);
    }

    // warp-local reductions: four samples + deferred Sigma(y^2) partial
    #pragma unroll
    for (int o = 16; o; o >>= 1) {
        q0  += __shfl_xor_sync(0xffffffffu, q0,  o);
        q0s += __shfl_xor_sync(0xffffffffu, q0s, o);
        q0y += __shfl_xor_sync(0xffffffffu, q0y, o);
        q1  += __shfl_xor_sync(0xffffffffu, q1,  o);
        q1s += __shfl_xor_sync(0xffffffffu, q1s, o);
        q1y += __shfl_xor_sync(0xffffffffu, q1y, o);
        q2  += __shfl_xor_sync(0xffffffffu, q2,  o);
        q2s += __shfl_xor_sync(0xffffffffu, q2s, o);
        q2y += __shfl_xor_sync(0xffffffffu, q2y, o);
        q3  += __shfl_xor_sync(0xffffffffu, q3,  o);
        q3s += __shfl_xor_sync(0xffffffffu, q3s, o);
        q3y += __shfl_xor_sync(0xffffffffu, q3y, o);
        sy2p += __shfl_xor_sync(0xffffffffu, sy2p, o);
    }
    const float i0 = __frcp_rn(q0);
    const float i1 = __frcp_rn(q1);
    const float i2 = __frcp_rn(q2);
    const float i3 = __frcp_rn(q3);
    float acc = fmaf(i0 * i0, q0s, -2.0f * i0 * q0y)
              + fmaf(i1 * i1, q1s, -2.0f * i1 * q1y)
              + fmaf(i2 * i2, q2s, -2.0f * i2 * q2y)
              + fmaf(i3 * i3, q3s, -2.0f * i3 * q3y)
              + (float)S_DIM * sy2p;

    // ---- block combine (single barrier) + fused grid reduction ----
    if (lane == 0) fin[warp] = acc;
    __syncthreads();
    if (tid == 0) {
        float tot = fin[0];
        #pragma unroll
        for (int w = 1; w < NWARPS; w++) tot += fin[w];
        g_partial[b] = tot;
        __threadfence();
        unsigned t = atomicAdd(&g_ticket, 1u);
        is_last = (t == B_DIM - 1) ? 1 : 0;
    }
    __syncthreads();

    if (is_last) {
        if (tid < B_DIM) {                     // warps 0..3
            float v = __ldcg(&g_partial[tid]);
            #pragma unroll
            for (int o = 16; o; o >>= 1) v += __shfl_xor_sync(0xffffffffu, v, o);
            if (lane == 0) fin[warp] = v;
        }
        __syncthreads();
        if (tid == 0) {
            float tot = fin[0] + fin[1] + fin[2] + fin[3];
            out[0] = tot * (1.0f / ((float)S_DIM * (float)B_DIM * (float)D_DIM));
            g_ticket = 0u;                      // reset for next graph replay
        }
    }
}

extern "C" void kernel_launch(void* const* d_in, const int* in_sizes, int n_in,
                              void* d_out, int out_size)
{
    const float* theta = (const float*)d_in[0];  // [B, D]
    const float* y     = (const float*)d_in[1];  // [B, D]
    const float* noise = (const float*)d_in[2];  // [S, B, D]
    float* out = (float*)d_out;

    cudaFuncSetAttribute(pl_fused,
                         cudaFuncAttributeMaxDynamicSharedMemorySize,
                         SMEM_BYTES);
    pl_fused<<<B_DIM, THREADS, SMEM_BYTES>>>(theta, y, noise, out);
}

// round 16
// speedup vs baseline: 1.0194x; 1.0194x over previous
#include <cuda_runtime.h>

// S=64, B=128, D=10000 fixed by the reference.
#define D_DIM   10000
#define D4      2500
#define NU      1250          // 32-byte units per row
#define NITER   39            // 39*32 = 1248 units; tail = 2 units (lane<2)
#define S_DIM   64
#define B_DIM   128
#define THREADS 512
#define NWARPS  16
#define SMEM_BYTES (2 * D_DIM * sizeof(float))   // 80000 B

#define L2E 1.4426950408889634f

__device__ float    g_partial[B_DIM];
__device__ unsigned g_ticket;      // zero-init; reset by last CTA each launch

__device__ __forceinline__ float ex2f(float x) {
    float r;
    asm("ex2.approx.ftz.f32 %0, %1;" : "=f"(r) : "f"(x));
    return r;
}

struct F8 { float4 a, b; };

// 256-bit streaming global load (sm_100a LDG.E.256)
__device__ __forceinline__ F8 ldg256cs(const void* p) {
    unsigned r0, r1, r2, r3, r4, r5, r6, r7;
    asm("ld.global.cs.v8.b32 {%0,%1,%2,%3,%4,%5,%6,%7}, [%8];"
        : "=r"(r0), "=r"(r1), "=r"(r2), "=r"(r3),
          "=r"(r4), "=r"(r5), "=r"(r6), "=r"(r7)
        : "l"(p));
    F8 v;
    v.a.x = __uint_as_float(r0); v.a.y = __uint_as_float(r1);
    v.a.z = __uint_as_float(r2); v.a.w = __uint_as_float(r3);
    v.b.x = __uint_as_float(r4); v.b.y = __uint_as_float(r5);
    v.b.z = __uint_as_float(r6); v.b.w = __uint_as_float(r7);
    return v;
}

// consume one quad (noise n, theta*log2e t, y yv) into one sample's accumulators
__device__ __forceinline__ void consume1(const float4& n, const float4& t,
                                         const float4& yv,
                                         float& sq, float& sq2, float& sqy)
{
    float qx = ex2f(fmaf(n.x, L2E, t.x));
    float qy = ex2f(fmaf(n.y, L2E, t.y));
    float qz = ex2f(fmaf(n.z, L2E, t.z));
    float qw = ex2f(fmaf(n.w, L2E, t.w));
    sq  += (qx + qy) + (qz + qw);
    sq2 = fmaf(qx, qx, sq2);   sq2 = fmaf(qy, qy, sq2);
    sq2 = fmaf(qz, qz, sq2);   sq2 = fmaf(qw, qw, sq2);
    sqy = fmaf(qx, yv.x, sqy); sqy = fmaf(qy, yv.y, sqy);
    sqy = fmaf(qz, yv.z, sqy); sqy = fmaf(qw, yv.w, sqy);
}

__global__ __launch_bounds__(THREADS, 1)   // 1 CTA/SM -> up to 128 regs/thread
void pl_fused(const float* __restrict__ theta,
              const float* __restrict__ y,
              const float* __restrict__ noise,
              float* __restrict__ out)
{
    extern __shared__ float sm[];          // [0,10000): theta_b*log2e  [10000,20000): y_b
    float* __restrict__ sth = sm;
    float* __restrict__ syy = sm + D_DIM;
    __shared__ float fin[NWARPS];
    __shared__ int   is_last;

    const int b    = blockIdx.x;
    const int tid  = threadIdx.x;
    const int lane = tid & 31;
    const int warp = tid >> 5;

    // ---- stage theta_b*log2e, y_b into shared; per-thread partial Sigma(y^2) ----
    float sy2p = 0.0f;
    {
        const float4* __restrict__ th4 = (const float4*)(theta + (size_t)b * D_DIM);
        const float4* __restrict__ yy4 = (const float4*)(y     + (size_t)b * D_DIM);
        float4* s_t = (float4*)sth;
        float4* s_y = (float4*)syy;
        for (int i = tid; i < D4; i += THREADS) {
            float4 t = __ldg(th4 + i);
            float4 v = __ldg(yy4 + i);
            sy2p = fmaf(v.x, v.x, sy2p);
            sy2p = fmaf(v.y, v.y, sy2p);
            sy2p = fmaf(v.z, v.z, sy2p);
            sy2p = fmaf(v.w, v.w, sy2p);
            t.x *= L2E; t.y *= L2E; t.z *= L2E; t.w *= L2E;
            s_t[i] = t;
            s_y[i] = v;
        }
    }
    __syncthreads();

    const float4* __restrict__ st4 = (const float4*)sth;
    const float4* __restrict__ sy4 = (const float4*)syy;

    // ---- single pass: warp owns samples 4*warp .. 4*warp+3 ----
    const size_t rowbytes = (size_t)B_DIM * D_DIM * sizeof(float); // sample stride
    const char* __restrict__ nz0 =
        (const char*)noise + ((size_t)(4 * warp) * B_DIM + b) * D_DIM * sizeof(float);
    const char* __restrict__ nz1 = nz0 + rowbytes;
    const char* __restrict__ nz2 = nz1 + rowbytes;
    const char* __restrict__ nz3 = nz2 + rowbytes;

    float q0 = 0.f, q0s = 0.f, q0y = 0.f;
    float q1 = 0.f, q1s = 0.f, q1y = 0.f;
    float q2 = 0.f, q2s = 0.f, q2y = 0.f;
    float q3 = 0.f, q3s = 0.f, q3y = 0.f;

    // depth-2 rotating pipeline per sample, 32-byte units (LDG.256)
    const size_t lb = (size_t)lane * 32;
    F8 P0[2], P1[2], P2[2], P3[2];
    #pragma unroll
    for (int k = 0; k < 2; k++) {
        const size_t off = (size_t)k * 1024 + lb;
        P0[k] = ldg256cs(nz0 + off);
        P1[k] = ldg256cs(nz1 + off);
        P2[k] = ldg256cs(nz2 + off);
        P3[k] = ldg256cs(nz3 + off);
    }

    // main: blocks 0..36 consume, reload block i+2 (last reload = block 38)
    #pragma unroll 2
    for (int i = 0; i <= 36; i++) {
        const int u  = i * 32 + lane;        // 32B-unit index
        const int k  = i & 1;
        const int f  = 2 * u;                // float4 index
        float4 t0 = st4[f],     y0 = sy4[f];
        float4 t1 = st4[f + 1], y1 = sy4[f + 1];
        consume1(P0[k].a, t0, y0, q0, q0s, q0y);
        consume1(P0[k].b, t1, y1, q0, q0s, q0y);
        consume1(P1[k].a, t0, y0, q1, q1s, q1y);
        consume1(P1[k].b, t1, y1, q1, q1s, q1y);
        consume1(P2[k].a, t0, y0, q2, q2s, q2y);
        consume1(P2[k].b, t1, y1, q2, q2s, q2y);
        consume1(P3[k].a, t0, y0, q3, q3s, q3y);
        consume1(P3[k].b, t1, y1, q3, q3s, q3y);
        const size_t off = (size_t)(u + 64) * 32;   // block i+2
        P0[k] = ldg256cs(nz0 + off);
        P1[k] = ldg256cs(nz1 + off);
        P2[k] = ldg256cs(nz2 + off);
        P3[k] = ldg256cs(nz3 + off);
    }

    // tail loads (lane<2): units 1248,1249 -> issued before epilogue consume
    F8 t0f, t1f, t2f, t3f;
    if (lane < 2) {
        const size_t off = (size_t)(1248 + lane) * 32;
        t0f = ldg256cs(nz0 + off);
        t1f = ldg256cs(nz1 + off);
        t2f = ldg256cs(nz2 + off);
        t3f = ldg256cs(nz3 + off);
    }

    // epilogue: blocks 37 (P[1]) and 38 (P[0]), no reloads
    #pragma unroll
    for (int i = 37; i <= 38; i++) {
        const int u = i * 32 + lane;
        const int k = i & 1;
        const int f = 2 * u;
        float4 t0 = st4[f],     y0 = sy4[f];
        float4 t1 = st4[f + 1], y1 = sy4[f + 1];
        consume1(P0[k].a, t0, y0, q0, q0s, q0y);
        consume1(P0[k].b, t1, y1, q0, q0s, q0y);
        consume1(P1[k].a, t0, y0, q1, q1s, q1y);
        consume1(P1[k].b, t1, y1, q1, q1s, q1y);
        consume1(P2[k].a, t0, y0, q2, q2s, q2y);
        consume1(P2[k].b, t1, y1, q2, q2s, q2y);
        consume1(P3[k].a, t0, y0, q3, q3s, q3y);
        consume1(P3[k].b, t1, y1, q3, q3s, q3y);
    }
    // tail units 1248..1249 (float4 idx 2496..2499)
    if (lane < 2) {
        const int f = 2 * (1248 + lane);
        float4 t0 = st4[f],     y0 = sy4[f];
        float4 t1 = st4[f + 1], y1 = sy4[f + 1];
        consume1(t0f.a, t0, y0, q0, q0s, q0y);
        consume1(t0f.b, t1, y1, q0, q0s, q0y);
        consume1(t1f.a, t0, y0, q1, q1s, q1y);
        consume1(t1f.b, t1, y1, q1, q1s, q1y);
        consume1(t2f.a, t0, y0, q2, q2s, q2y);
        consume1(t2f.b, t1, y1, q2, q2s, q2y);
        consume1(t3f.a, t0, y0, q3, q3s, q3y);
        consume1(t3f.b, t1, y1, q3, q3s, q3y);
    }

    // warp-local reductions: four samples + deferred Sigma(y^2) partial
    #pragma unroll
    for (int o = 16; o; o >>= 1) {
        q0  += __shfl_xor_sync(0xffffffffu, q0,  o);
        q0s += __shfl_xor_sync(0xffffffffu, q0s, o);
        q0y += __shfl_xor_sync(0xffffffffu, q0y, o);
        q1  += __shfl_xor_sync(0xffffffffu, q1,  o);
        q1s += __shfl_xor_sync(0xffffffffu, q1s, o);
        q1y += __shfl_xor_sync(0xffffffffu, q1y, o);
        q2  += __shfl_xor_sync(0xffffffffu, q2,  o);
        q2s += __shfl_xor_sync(0xffffffffu, q2s, o);
        q2y += __shfl_xor_sync(0xffffffffu, q2y, o);
        q3  += __shfl_xor_sync(0xffffffffu, q3,  o);
        q3s += __shfl_xor_sync(0xffffffffu, q3s, o);
        q3y += __shfl_xor_sync(0xffffffffu, q3y, o);
        sy2p += __shfl_xor_sync(0xffffffffu, sy2p, o);
    }
    const float i0 = __frcp_rn(q0);
    const float i1 = __frcp_rn(q1);
    const float i2 = __frcp_rn(q2);
    const float i3 = __frcp_rn(q3);
    float acc = fmaf(i0 * i0, q0s, -2.0f * i0 * q0y)
              + fmaf(i1 * i1, q1s, -2.0f * i1 * q1y)
              + fmaf(i2 * i2, q2s, -2.0f * i2 * q2y)
              + fmaf(i3 * i3, q3s, -2.0f * i3 * q3y)
              + (float)S_DIM * sy2p;

    // ---- block combine (single barrier) + fused grid reduction ----
    if (lane == 0) fin[warp] = acc;
    __syncthreads();
    if (tid == 0) {
        float tot = fin[0];
        #pragma unroll
        for (int w = 1; w < NWARPS; w++) tot += fin[w];
        g_partial[b] = tot;
        __threadfence();
        unsigned t = atomicAdd(&g_ticket, 1u);
        is_last = (t == B_DIM - 1) ? 1 : 0;
    }
    __syncthreads();

    if (is_last) {
        if (tid < B_DIM) {                     // warps 0..3
            float v = __ldcg(&g_partial[tid]);
            #pragma unroll
            for (int o = 16; o; o >>= 1) v += __shfl_xor_sync(0xffffffffu, v, o);
            if (lane == 0) fin[warp] = v;
        }
        __syncthreads();
        if (tid == 0) {
            float tot = fin[0] + fin[1] + fin[2] + fin[3];
            out[0] = tot * (1.0f / ((float)S_DIM * (float)B_DIM * (float)D_DIM));
            g_ticket = 0u;                      // reset for next graph replay
        }
    }
}

extern "C" void kernel_launch(void* const* d_in, const int* in_sizes, int n_in,
                              void* d_out, int out_size)
{
    const float* theta = (const float*)d_in[0];  // [B, D]
    const float* y     = (const float*)d_in[1];  // [B, D]
    const float* noise = (const float*)d_in[2];  // [S, B, D]
    float* out = (float*)d_out;

    cudaFuncSetAttribute(pl_fused,
                         cudaFuncAttributeMaxDynamicSharedMemorySize,
                         SMEM_BYTES);
    pl_fused<<<B_DIM, THREADS, SMEM_BYTES>>>(theta, y, noise, out);
}